// round 4
// baseline (speedup 1.0000x reference)
#include <cuda_runtime.h>
#include <cuda_bf16.h>

// Problem dims
#define NB 65536   // batch rows
#define NC 1024    // channel dim
#define ND 256     // latent dim
#define NK 2048    // codebook size
#define NCB 4      // num codebooks

// Output layout (float32): [z_q (NB*NC)][vq_loss][enc_loss][cbk_loss][codes (NB*NCB)][latents (NB*NCB*ND)]
#define O_SC   (NB * NC)
#define O_CODE (O_SC + 3)
#define O_LAT  (O_CODE + NB * NCB)
#define O_TOT  (O_LAT + NB * NCB * ND)

// Scratch (static device globals)
__device__ float g_res[NB * NC];    // residual (256 MB)
__device__ float g_zqi[NB * NC];    // z_q_i GEMM output (256 MB)
__device__ float g_ze[NB * ND];     // z_e (64 MB)
__device__ float g_zqst[NB * ND];   // straight-through z_q_st (64 MB)
__device__ float g_cbn[NK];
__device__ float g_zn[NB];
__device__ int   g_idx[NB];
__device__ float g_rowloss[NB];

// ---------------------------------------------------------------------------
__global__ void k_copy_res(const float* __restrict__ z) {
    int i = blockIdx.x * blockDim.x + threadIdx.x;
    int stride = gridDim.x * blockDim.x;
    const float4* src = (const float4*)z;
    float4* dst = (float4*)g_res;
    const int n4 = NB * NC / 4;
    for (int j = i; j < n4; j += stride) dst[j] = src[j];
}

// ---------------------------------------------------------------------------
// Tiled fp32 GEMM: C[M,N] = A[M,K] @ B[K,N] + bias[N].
// Each output is a single ascending-k FFMA chain (bit-matches cuBLAS SGEMM).
__global__ void __launch_bounds__(256) k_gemm_bias(
    const float* __restrict__ A, const float* __restrict__ Bm,
    const float* __restrict__ bias, float* __restrict__ C,
    int M, int N, int K)
{
    const int BM = 128, BN = 64, BK = 16, TM = 8, TN = 4;
    __shared__ float As[BK][BM + 4];
    __shared__ float Bs[BK][BN];
    int tid = threadIdx.x;
    int tx = tid & 15;
    int ty = tid >> 4;
    int row0 = blockIdx.y * BM;
    int col0 = blockIdx.x * BN;

    float acc[TM][TN];
#pragma unroll
    for (int m = 0; m < TM; m++)
#pragma unroll
        for (int n = 0; n < TN; n++) acc[m][n] = 0.0f;

    for (int k0 = 0; k0 < K; k0 += BK) {
#pragma unroll
        for (int i = 0; i < 2; i++) {
            int f4 = i * 256 + tid;
            int r  = f4 >> 2;
            int c4 = f4 & 3;
            float4 v = *(const float4*)&A[(long)(row0 + r) * K + k0 + c4 * 4];
            As[c4 * 4 + 0][r] = v.x;
            As[c4 * 4 + 1][r] = v.y;
            As[c4 * 4 + 2][r] = v.z;
            As[c4 * 4 + 3][r] = v.w;
        }
        {
            int r  = tid >> 4;
            int c4 = tid & 15;
            float4 v = *(const float4*)&Bm[(long)(k0 + r) * N + col0 + c4 * 4];
            *(float4*)&Bs[r][c4 * 4] = v;
        }
        __syncthreads();
#pragma unroll
        for (int kk = 0; kk < BK; kk++) {
            float a[TM], b[TN];
            float4 a0 = *(const float4*)&As[kk][ty * TM];
            float4 a1 = *(const float4*)&As[kk][ty * TM + 4];
            a[0] = a0.x; a[1] = a0.y; a[2] = a0.z; a[3] = a0.w;
            a[4] = a1.x; a[5] = a1.y; a[6] = a1.z; a[7] = a1.w;
            float4 b0 = *(const float4*)&Bs[kk][tx * TN];
            b[0] = b0.x; b[1] = b0.y; b[2] = b0.z; b[3] = b0.w;
#pragma unroll
            for (int m = 0; m < TM; m++)
#pragma unroll
                for (int n = 0; n < TN; n++) acc[m][n] = fmaf(a[m], b[n], acc[m][n]);
        }
        __syncthreads();
    }
#pragma unroll
    for (int m = 0; m < TM; m++) {
        long orow = row0 + ty * TM + m;
#pragma unroll
        for (int n = 0; n < TN; n++) {
            int oc = col0 + tx * TN + n;
            C[orow * N + oc] = __fadd_rn(acc[m][n], bias[oc]);
        }
    }
}

// ---------------------------------------------------------------------------
// XLA-GPU-style vectorized row sum-of-squares: one warp per 256-float row.
// Lane l accumulates float4 [4l..4l+3] then [128+4l..128+4l+3] sequentially,
// separate mul/add (no FMA), then shfl-down tree 16..1. Valid in lane 0.
__device__ __forceinline__ float row_sumsq_vec4(const float* __restrict__ row) {
    int l = threadIdx.x & 31;
    float4 a = *(const float4*)&row[4 * l];
    float4 b = *(const float4*)&row[128 + 4 * l];
    float s;
    s = __fmul_rn(a.x, a.x);
    s = __fadd_rn(s, __fmul_rn(a.y, a.y));
    s = __fadd_rn(s, __fmul_rn(a.z, a.z));
    s = __fadd_rn(s, __fmul_rn(a.w, a.w));
    s = __fadd_rn(s, __fmul_rn(b.x, b.x));
    s = __fadd_rn(s, __fmul_rn(b.y, b.y));
    s = __fadd_rn(s, __fmul_rn(b.z, b.z));
    s = __fadd_rn(s, __fmul_rn(b.w, b.w));
#pragma unroll
    for (int off = 16; off > 0; off >>= 1)
        s = __fadd_rn(s, __shfl_down_sync(0xffffffffu, s, off));
    return s;
}

__global__ void k_cbn(const float* __restrict__ cb) {
    int w = threadIdx.x >> 5;
    int k = blockIdx.x * 4 + w;
    float s = row_sumsq_vec4(cb + (long)k * ND);
    if ((threadIdx.x & 31) == 0) g_cbn[k] = s;
}

__global__ void k_rownorm() {
    int w = threadIdx.x >> 5;
    int b = blockIdx.x * 4 + w;
    float s = row_sumsq_vec4(g_ze + (long)b * ND);
    if ((threadIdx.x & 31) == 0) g_zn[b] = s;
}

// ---------------------------------------------------------------------------
// Fused distance GEMM + argmin. d = fl(fl(zn - fl(2*dot)) + cbn).
// Dot is an ascending-k FFMA chain. Lowest-index tiebreak (jnp.argmin).
__global__ void __launch_bounds__(256) k_dist(const float* __restrict__ cb) {
    const int BM = 128, BN = 128, BK = 32, TM = 8, TN = 8;
    __shared__ float Zs[BK][BM + 4];
    __shared__ float Cs[BK][BN + 4];
    int tid = threadIdx.x;
    int tx = tid & 15;
    int ty = tid >> 4;
    int row0 = blockIdx.x * BM;

    float best[TM];
    int   bidx[TM];
    float zn[TM];
#pragma unroll
    for (int m = 0; m < TM; m++) {
        best[m] = 3.4e38f;
        bidx[m] = 0;
        zn[m] = g_zn[row0 + ty * TM + m];
    }

    for (int n0 = 0; n0 < NK; n0 += BN) {
        float acc[TM][TN];
#pragma unroll
        for (int m = 0; m < TM; m++)
#pragma unroll
            for (int n = 0; n < TN; n++) acc[m][n] = 0.0f;

        for (int d0 = 0; d0 < ND; d0 += BK) {
#pragma unroll
            for (int i = 0; i < 4; i++) {
                int f4 = i * 256 + tid;
                int r  = f4 >> 3;
                int c4 = f4 & 7;
                float4 v = *(const float4*)&g_ze[(long)(row0 + r) * ND + d0 + c4 * 4];
                Zs[c4 * 4 + 0][r] = v.x;
                Zs[c4 * 4 + 1][r] = v.y;
                Zs[c4 * 4 + 2][r] = v.z;
                Zs[c4 * 4 + 3][r] = v.w;
            }
#pragma unroll
            for (int i = 0; i < 4; i++) {
                int f4 = i * 256 + tid;
                int r  = f4 >> 3;
                int c4 = f4 & 7;
                float4 v = *(const float4*)&cb[(long)(n0 + r) * ND + d0 + c4 * 4];
                Cs[c4 * 4 + 0][r] = v.x;
                Cs[c4 * 4 + 1][r] = v.y;
                Cs[c4 * 4 + 2][r] = v.z;
                Cs[c4 * 4 + 3][r] = v.w;
            }
            __syncthreads();
#pragma unroll
            for (int kk = 0; kk < BK; kk++) {
                float a[8], b[8];
                float4 t0 = *(const float4*)&Zs[kk][ty * 8];
                float4 t1 = *(const float4*)&Zs[kk][ty * 8 + 4];
                a[0] = t0.x; a[1] = t0.y; a[2] = t0.z; a[3] = t0.w;
                a[4] = t1.x; a[5] = t1.y; a[6] = t1.z; a[7] = t1.w;
                float4 u0 = *(const float4*)&Cs[kk][tx * 8];
                float4 u1 = *(const float4*)&Cs[kk][tx * 8 + 4];
                b[0] = u0.x; b[1] = u0.y; b[2] = u0.z; b[3] = u0.w;
                b[4] = u1.x; b[5] = u1.y; b[6] = u1.z; b[7] = u1.w;
#pragma unroll
                for (int m = 0; m < TM; m++)
#pragma unroll
                    for (int n = 0; n < TN; n++) acc[m][n] = fmaf(a[m], b[n], acc[m][n]);
            }
            __syncthreads();
        }
#pragma unroll
        for (int n = 0; n < TN; n++) {
            int gc = n0 + tx * 8 + n;
            float cn = g_cbn[gc];
#pragma unroll
            for (int m = 0; m < TM; m++) {
                float d = __fadd_rn(__fsub_rn(zn[m], __fmul_rn(2.0f, acc[m][n])), cn);
                if (d < best[m] || (d == best[m] && gc < bidx[m])) { best[m] = d; bidx[m] = gc; }
            }
        }
    }
#pragma unroll
    for (int off = 8; off > 0; off >>= 1) {
#pragma unroll
        for (int m = 0; m < TM; m++) {
            float ov = __shfl_down_sync(0xffffffffu, best[m], off);
            int   oi = __shfl_down_sync(0xffffffffu, bidx[m], off);
            if (ov < best[m] || (ov == best[m] && oi < bidx[m])) { best[m] = ov; bidx[m] = oi; }
        }
    }
    if (tx == 0) {
#pragma unroll
        for (int m = 0; m < TM; m++) g_idx[row0 + ty * TM + m] = bidx[m];
    }
}

// ---------------------------------------------------------------------------
// Gather + straight-through: z_q_st = fl(z_e + fl(cb[idx] - z_e)),
// replicating the reference's elementwise arithmetic exactly.
// Also: commit-loss partials, latents, codes. One block (256 thr) per row.
__global__ void k_gather(const float* __restrict__ cb, float* __restrict__ out,
                         int cbi, int writeFull) {
    int b = blockIdx.x;
    int t = threadIdx.x;
    int idx = g_idx[b];

    float ze = g_ze[(long)b * ND + t];
    float cv = cb[(long)idx * ND + t];
    // straight-through forward value, ref rounding: z_e + (cb - z_e)
    g_zqst[(long)b * ND + t] = __fadd_rn(ze, __fsub_rn(cv, ze));

    float df = ze - cv;
    float s = df * df;
#pragma unroll
    for (int off = 16; off > 0; off >>= 1) s += __shfl_down_sync(0xffffffffu, s, off);
    __shared__ float ws[8];
    if ((t & 31) == 0) ws[t >> 5] = s;
    __syncthreads();
    if (t == 0) {
        float tot = 0.0f;
#pragma unroll
        for (int w = 0; w < 8; w++) tot += ws[w];
        g_rowloss[b] = (cbi == 0) ? tot : (g_rowloss[b] + tot);
    }

    if (writeFull) {
        out[O_LAT + (long)b * NC + cbi * ND + t] = ze;
        if (t == 0) out[O_CODE + (long)b * NCB + cbi] = (float)idx;
    }
}

// ---------------------------------------------------------------------------
// Apply z_q_i: z_q += z_q_i (ref-style chain from 0), residual -= z_q_i.
__global__ void k_apply(float* __restrict__ out, int cbi) {
    int i = blockIdx.x * blockDim.x + threadIdx.x;
    int stride = gridDim.x * blockDim.x;
    const float4* qi = (const float4*)g_zqi;
    float4* rr = (float4*)g_res;
    float4* zq = (float4*)out;
    const int n4 = NB * NC / 4;
    for (int j = i; j < n4; j += stride) {
        float4 q = qi[j];
        float4 r = rr[j];
        rr[j] = make_float4(__fsub_rn(r.x, q.x), __fsub_rn(r.y, q.y),
                            __fsub_rn(r.z, q.z), __fsub_rn(r.w, q.w));
        if (cbi == 0) {
            zq[j] = q;
        } else {
            float4 p = zq[j];
            zq[j] = make_float4(__fadd_rn(p.x, q.x), __fadd_rn(p.y, q.y),
                                __fadd_rn(p.z, q.z), __fadd_rn(p.w, q.w));
        }
    }
}

// ---------------------------------------------------------------------------
__global__ void k_loss(float* __restrict__ out, int writeFull) {
    __shared__ float sm[1024];
    int t = threadIdx.x;
    float s = 0.0f;
    for (int i = t; i < NB; i += 1024) s += g_rowloss[i];
    sm[t] = s;
    __syncthreads();
    for (int off = 512; off > 0; off >>= 1) {
        if (t < off) sm[t] += sm[t + off];
        __syncthreads();
    }
    if (t == 0 && writeFull) {
        float enc = 0.25f * sm[0] / 16777216.0f;
        out[O_SC + 0] = enc;
        out[O_SC + 1] = enc;
        out[O_SC + 2] = 0.0f;
    }
}

// ---------------------------------------------------------------------------
extern "C" void kernel_launch(void* const* d_in, const int* in_sizes, int n_in,
                              void* d_out, int out_size) {
    const float* z   = (const float*)d_in[0];
    const float* cbs = (const float*)d_in[1];
    const float* Wi  = (const float*)d_in[2];
    const float* bi  = (const float*)d_in[3];
    const float* Wo  = (const float*)d_in[4];
    const float* bo  = (const float*)d_in[5];
    float* out = (float*)d_out;
    int writeFull = (out_size >= O_TOT) ? 1 : 0;

    float *p_res, *p_ze, *p_zqst, *p_zqi;
    cudaGetSymbolAddress((void**)&p_res,  g_res);
    cudaGetSymbolAddress((void**)&p_ze,   g_ze);
    cudaGetSymbolAddress((void**)&p_zqst, g_zqst);
    cudaGetSymbolAddress((void**)&p_zqi,  g_zqi);

    k_copy_res<<<2048, 256>>>(z);

    for (int i = 0; i < NCB; i++) {
        const float* cb = cbs + (long)i * NK * ND;
        k_cbn<<<NK / 4, 128>>>(cb);
        // z_e = residual @ W_in[i] + b_in[i]    [NB,ND] K=NC
        k_gemm_bias<<<dim3(ND / 64, NB / 128), 256>>>(
            p_res, Wi + (long)i * NC * ND, bi + i * ND, p_ze, NB, ND, NC);
        k_rownorm<<<NB / 4, 128>>>();
        k_dist<<<NB / 128, 256>>>(cb);
        k_gather<<<NB, 256>>>(cb, out, i, writeFull);
        // z_q_i = z_q_st @ W_out[i] + b_out[i]  [NB,NC] K=ND
        k_gemm_bias<<<dim3(NC / 64, NB / 128), 256>>>(
            p_zqst, Wo + (long)i * ND * NC, bo + i * NC, p_zqi, NB, NC, ND);
        k_apply<<<2048, 256>>>(out, i);
    }

    k_loss<<<1, 1024>>>(out, writeFull);
}

// round 6
// speedup vs baseline: 1.7324x; 1.7324x over previous
#include <cuda_runtime.h>
#include <cuda_bf16.h>
#include <cstdint>

// Problem dims
#define NB 65536
#define NC 1024
#define ND 256
#define NK 2048
#define NCB 4

// Output layout (float32): [z_q][vq_loss][enc_loss][cbk_loss][codes][latents]
#define O_SC   (NB * NC)
#define O_CODE (O_SC + 3)
#define O_LAT  (O_CODE + NB * NCB)
#define O_TOT  (O_LAT + NB * NCB * ND)

// Scratch
__device__ float g_res[NB * NC];          // residual (256 MB)
__device__ float g_ze[NB * ND];           // z_e (64 MB)
__device__ float g_zqst[NB * ND];         // straight-through (64 MB)
__device__ float g_dot[(size_t)NB * NK];  // bf16 tensor dots (512 MB)
__device__ float g_cbn[NK];
__device__ float g_zn[NB];
__device__ int   g_idx[NB];
__device__ float g_rowloss[NB];

// bf16x2 pack: element order [a, b]
__device__ __forceinline__ uint32_t pack_bf16x2(float a, float b) {
    uint32_t r;
    asm("cvt.rn.satfinite.bf16x2.f32 %0, %1, %2;" : "=r"(r) : "f"(b), "f"(a));
    return r;
}

// ===========================================================================
__global__ void k_copy_res(const float* __restrict__ z) {
    int i = blockIdx.x * blockDim.x + threadIdx.x;
    int stride = gridDim.x * blockDim.x;
    const float4* src = (const float4*)z;
    float4* dst = (float4*)g_res;
    const int n4 = NB * NC / 4;
    for (int j = i; j < n4; j += stride) dst[j] = src[j];
}

// ===========================================================================
// fp32 SIMT GEMM body (bit-identical arithmetic to round-4 pass)
#define GEMM_BODY(A_, B_, K_, N_) \
    const int BM = 128, BN = 64, BK = 16, TM = 8, TN = 4; \
    __shared__ float As[BK][BM + 4]; \
    __shared__ float Bs[BK][BN]; \
    int tid = threadIdx.x; \
    int tx = tid & 15; \
    int ty = tid >> 4; \
    int row0 = blockIdx.y * BM; \
    int col0 = blockIdx.x * BN; \
    float acc[TM][TN]; \
    _Pragma("unroll") for (int m = 0; m < TM; m++) \
        _Pragma("unroll") for (int n = 0; n < TN; n++) acc[m][n] = 0.0f; \
    for (int k0 = 0; k0 < (K_); k0 += BK) { \
        _Pragma("unroll") for (int i = 0; i < 2; i++) { \
            int f4 = i * 256 + tid; \
            int r = f4 >> 2, c4 = f4 & 3; \
            float4 v = *(const float4*)&(A_)[(long)(row0 + r) * (K_) + k0 + c4 * 4]; \
            As[c4 * 4 + 0][r] = v.x; As[c4 * 4 + 1][r] = v.y; \
            As[c4 * 4 + 2][r] = v.z; As[c4 * 4 + 3][r] = v.w; \
        } \
        { \
            int r = tid >> 4, c4 = tid & 15; \
            float4 v = *(const float4*)&(B_)[(long)(k0 + r) * (N_) + col0 + c4 * 4]; \
            *(float4*)&Bs[r][c4 * 4] = v; \
        } \
        __syncthreads(); \
        _Pragma("unroll") for (int kk = 0; kk < BK; kk++) { \
            float a[TM], b[TN]; \
            float4 a0 = *(const float4*)&As[kk][ty * TM]; \
            float4 a1 = *(const float4*)&As[kk][ty * TM + 4]; \
            a[0]=a0.x; a[1]=a0.y; a[2]=a0.z; a[3]=a0.w; \
            a[4]=a1.x; a[5]=a1.y; a[6]=a1.z; a[7]=a1.w; \
            float4 b0 = *(const float4*)&Bs[kk][tx * TN]; \
            b[0]=b0.x; b[1]=b0.y; b[2]=b0.z; b[3]=b0.w; \
            _Pragma("unroll") for (int m = 0; m < TM; m++) \
                _Pragma("unroll") for (int n = 0; n < TN; n++) \
                    acc[m][n] = fmaf(a[m], b[n], acc[m][n]); \
        } \
        __syncthreads(); \
    }

// z_e = residual @ W_in + b_in
__global__ void __launch_bounds__(256) k_gemm_ze(
    const float* __restrict__ A, const float* __restrict__ Bm,
    const float* __restrict__ bias, float* __restrict__ C, int K_, int N_)
{
    GEMM_BODY(A, Bm, K_, N_)
#pragma unroll
    for (int m = 0; m < TM; m++) {
        long orow = row0 + ty * TM + m;
#pragma unroll
        for (int n = 0; n < TN; n++) {
            int oc = col0 + tx * TN + n;
            C[orow * N_ + oc] = __fadd_rn(acc[m][n], bias[oc]);
        }
    }
}

// z_q_i = z_q_st @ W_out + b_out, fused apply: res -= qi, zq (+)= qi
__global__ void __launch_bounds__(256) k_gemm_out(
    const float* __restrict__ A, const float* __restrict__ Bm,
    const float* __restrict__ bias, float* __restrict__ zq,
    int K_, int N_, int cbi)
{
    GEMM_BODY(A, Bm, K_, N_)
#pragma unroll
    for (int m = 0; m < TM; m++) {
        long orow = row0 + ty * TM + m;
#pragma unroll
        for (int n = 0; n < TN; n++) {
            int oc = col0 + tx * TN + n;
            long off = orow * N_ + oc;
            float qi = __fadd_rn(acc[m][n], bias[oc]);
            g_res[off] = __fsub_rn(g_res[off], qi);
            zq[off] = (cbi == 0) ? qi : __fadd_rn(zq[off], qi);
        }
    }
}

// ===========================================================================
// Row sum-of-squares (bit-identical to round-4 pass)
__device__ __forceinline__ float row_sumsq_vec4(const float* __restrict__ row) {
    int l = threadIdx.x & 31;
    float4 a = *(const float4*)&row[4 * l];
    float4 b = *(const float4*)&row[128 + 4 * l];
    float s;
    s = __fmul_rn(a.x, a.x);
    s = __fadd_rn(s, __fmul_rn(a.y, a.y));
    s = __fadd_rn(s, __fmul_rn(a.z, a.z));
    s = __fadd_rn(s, __fmul_rn(a.w, a.w));
    s = __fadd_rn(s, __fmul_rn(b.x, b.x));
    s = __fadd_rn(s, __fmul_rn(b.y, b.y));
    s = __fadd_rn(s, __fmul_rn(b.z, b.z));
    s = __fadd_rn(s, __fmul_rn(b.w, b.w));
#pragma unroll
    for (int off = 16; off > 0; off >>= 1)
        s = __fadd_rn(s, __shfl_down_sync(0xffffffffu, s, off));
    return s;
}

__global__ void k_cbn(const float* __restrict__ cb) {
    int w = threadIdx.x >> 5;
    int k = blockIdx.x * 4 + w;
    float s = row_sumsq_vec4(cb + (long)k * ND);
    if ((threadIdx.x & 31) == 0) g_cbn[k] = s;
}
__global__ void k_rownorm() {
    int w = threadIdx.x >> 5;
    int b = blockIdx.x * 4 + w;
    float s = row_sumsq_vec4(g_ze + (long)b * ND);
    if ((threadIdx.x & 31) == 0) g_zn[b] = s;
}

// ===========================================================================
// bf16 mma.sync dot GEMM: g_dot[row, code] = ze_bf16[row] . cb_bf16[code]
// CTA = 256 threads / 8 warps, 128 rows. A tile loaded once (128x256 bf16,
// padded stride 264 -> conflict-free fragment loads). 32 chunks of 64 codes.
// Warp computes 16x64; m16n8k16 row.col fragments loaded by direct LDS.
#define ASTRIDE 264
#define DOT_SMEM_A 0
#define DOT_SMEM_B (128 * ASTRIDE * 2)                 // 67584
#define DOT_SMEM_TOTAL (DOT_SMEM_B + 64 * ASTRIDE * 2) // 101376

__device__ __forceinline__ void mma16816(float* c, uint32_t a0, uint32_t a1,
                                         uint32_t a2, uint32_t a3,
                                         uint32_t b0, uint32_t b1) {
    asm volatile(
        "mma.sync.aligned.m16n8k16.row.col.f32.bf16.bf16.f32 "
        "{%0,%1,%2,%3}, {%4,%5,%6,%7}, {%8,%9}, {%0,%1,%2,%3};"
        : "+f"(c[0]), "+f"(c[1]), "+f"(c[2]), "+f"(c[3])
        : "r"(a0), "r"(a1), "r"(a2), "r"(a3), "r"(b0), "r"(b1));
}

__global__ void __launch_bounds__(256) k_dots(const float* __restrict__ cb) {
    extern __shared__ char smem[];
    __nv_bfloat16* As = (__nv_bfloat16*)(smem + DOT_SMEM_A);
    __nv_bfloat16* Bs = (__nv_bfloat16*)(smem + DOT_SMEM_B);
    int tid = threadIdx.x;
    int wid = tid >> 5, lane = tid & 31;
    int gid = lane >> 2, tig = lane & 3;
    int row0 = blockIdx.x * 128;

    // Load A: 128 rows x 256 cols fp32 -> bf16 (each thread 32 float4 groups)
    for (int i = tid; i < 128 * 64; i += 256) {
        int r = i >> 6;
        int c = (i & 63) * 4;
        float4 v = *(const float4*)&g_ze[(long)(row0 + r) * ND + c];
        uint2 p = make_uint2(pack_bf16x2(v.x, v.y), pack_bf16x2(v.z, v.w));
        *(uint2*)&As[r * ASTRIDE + c] = p;
    }

    for (int chunk = 0; chunk < 32; chunk++) {
        int n0 = chunk * 64;
        // Load B: 64 codes x 256 cols fp32 -> bf16
        for (int i = tid; i < 64 * 64; i += 256) {
            int r = i >> 6;
            int c = (i & 63) * 4;
            float4 v = *(const float4*)&cb[(long)(n0 + r) * ND + c];
            uint2 p = make_uint2(pack_bf16x2(v.x, v.y), pack_bf16x2(v.z, v.w));
            *(uint2*)&Bs[r * ASTRIDE + c] = p;
        }
        __syncthreads();

        float acc[8][4];
#pragma unroll
        for (int n8 = 0; n8 < 8; n8++)
#pragma unroll
            for (int j = 0; j < 4; j++) acc[n8][j] = 0.0f;

        int arow = wid * 16 + gid;
#pragma unroll
        for (int ks = 0; ks < 16; ks++) {
            int ak = ks * 16 + tig * 2;
            uint32_t a0 = *(const uint32_t*)&As[arow * ASTRIDE + ak];
            uint32_t a1 = *(const uint32_t*)&As[(arow + 8) * ASTRIDE + ak];
            uint32_t a2 = *(const uint32_t*)&As[arow * ASTRIDE + ak + 8];
            uint32_t a3 = *(const uint32_t*)&As[(arow + 8) * ASTRIDE + ak + 8];
#pragma unroll
            for (int n8 = 0; n8 < 8; n8++) {
                int brow = n8 * 8 + gid;
                uint32_t b0 = *(const uint32_t*)&Bs[brow * ASTRIDE + ak];
                uint32_t b1 = *(const uint32_t*)&Bs[brow * ASTRIDE + ak + 8];
                mma16816(acc[n8], a0, a1, a2, a3, b0, b1);
            }
        }

        // Store D fragments: lane holds D[gid][tig*2,+1] and D[gid+8][tig*2,+1]
        size_t rbase0 = (size_t)(row0 + wid * 16 + gid) * NK + n0;
        size_t rbase1 = rbase0 + (size_t)8 * NK;
#pragma unroll
        for (int n8 = 0; n8 < 8; n8++) {
            int col = n8 * 8 + tig * 2;
            *(float2*)&g_dot[rbase0 + col] = make_float2(acc[n8][0], acc[n8][1]);
            *(float2*)&g_dot[rbase1 + col] = make_float2(acc[n8][2], acc[n8][3]);
        }
        __syncthreads();
    }
}

// ===========================================================================
// Approx argmin over bf16 dots + exact fp32 rescore of candidates within MARGIN.
// Selection provably identical to exact full scan (margin >> 2*max approx err).
#define MARGIN 0.12f
__global__ void __launch_bounds__(256) k_argsel(const float* __restrict__ cb) {
    int w = threadIdx.x >> 5, l = threadIdx.x & 31;
    int row = blockIdx.x * 8 + w;
    const float* drow = &g_dot[(size_t)row * NK];
    float zn = g_zn[row];

    float dmin = 3.4e38f;
#pragma unroll 4
    for (int j = 0; j < NK / 32; j++) {
        int k = j * 32 + l;
        float da = zn - 2.0f * drow[k] + g_cbn[k];
        dmin = fminf(dmin, da);
    }
#pragma unroll
    for (int off = 16; off > 0; off >>= 1)
        dmin = fminf(dmin, __shfl_xor_sync(0xffffffffu, dmin, off));
    float thr = dmin + MARGIN;

    float best = 3.4e38f;
    int bidx = 0x40000000;
    const float* ze = &g_ze[(long)row * ND];
    for (int j = 0; j < NK / 32; j++) {
        int k = j * 32 + l;
        float da = zn - 2.0f * drow[k] + g_cbn[k];
        if (da <= thr) {
            // exact rescore: ascending-k FFMA chain (bit-identical to round-4 dist)
            const float* cr = &cb[(long)k * ND];
            float acc = 0.0f;
#pragma unroll 8
            for (int t = 0; t < ND; t++) acc = fmaf(ze[t], cr[t], acc);
            float de = __fadd_rn(__fsub_rn(zn, __fmul_rn(2.0f, acc)), g_cbn[k]);
            if (de < best || (de == best && k < bidx)) { best = de; bidx = k; }
        }
    }
#pragma unroll
    for (int off = 16; off > 0; off >>= 1) {
        float ov = __shfl_down_sync(0xffffffffu, best, off);
        int   oi = __shfl_down_sync(0xffffffffu, bidx, off);
        if (ov < best || (ov == best && oi < bidx)) { best = ov; bidx = oi; }
    }
    if (l == 0) g_idx[row] = bidx;
}

// ===========================================================================
__global__ void k_gather(const float* __restrict__ cb, float* __restrict__ out,
                         int cbi, int writeFull) {
    int b = blockIdx.x;
    int t = threadIdx.x;
    int idx = g_idx[b];

    float ze = g_ze[(long)b * ND + t];
    float cv = cb[(long)idx * ND + t];
    g_zqst[(long)b * ND + t] = __fadd_rn(ze, __fsub_rn(cv, ze));

    float df = ze - cv;
    float s = df * df;
#pragma unroll
    for (int off = 16; off > 0; off >>= 1) s += __shfl_down_sync(0xffffffffu, s, off);
    __shared__ float ws[8];
    if ((t & 31) == 0) ws[t >> 5] = s;
    __syncthreads();
    if (t == 0) {
        float tot = 0.0f;
#pragma unroll
        for (int w = 0; w < 8; w++) tot += ws[w];
        g_rowloss[b] = (cbi == 0) ? tot : (g_rowloss[b] + tot);
    }

    if (writeFull) {
        out[O_LAT + (long)b * NC + cbi * ND + t] = ze;
        if (t == 0) out[O_CODE + (long)b * NCB + cbi] = (float)idx;
    }
}

// ===========================================================================
__global__ void k_loss(float* __restrict__ out, int writeFull) {
    __shared__ float sm[1024];
    int t = threadIdx.x;
    float s = 0.0f;
    for (int i = t; i < NB; i += 1024) s += g_rowloss[i];
    sm[t] = s;
    __syncthreads();
    for (int off = 512; off > 0; off >>= 1) {
        if (t < off) sm[t] += sm[t + off];
        __syncthreads();
    }
    if (t == 0 && writeFull) {
        float enc = 0.25f * sm[0] / 16777216.0f;
        out[O_SC + 0] = enc;
        out[O_SC + 1] = enc;
        out[O_SC + 2] = 0.0f;
    }
}

// ===========================================================================
extern "C" void kernel_launch(void* const* d_in, const int* in_sizes, int n_in,
                              void* d_out, int out_size) {
    const float* z   = (const float*)d_in[0];
    const float* cbs = (const float*)d_in[1];
    const float* Wi  = (const float*)d_in[2];
    const float* bi  = (const float*)d_in[3];
    const float* Wo  = (const float*)d_in[4];
    const float* bo  = (const float*)d_in[5];
    float* out = (float*)d_out;
    int writeFull = (out_size >= O_TOT) ? 1 : 0;

    cudaFuncSetAttribute(k_dots, cudaFuncAttributeMaxDynamicSharedMemorySize, DOT_SMEM_TOTAL);

    float *p_res, *p_ze, *p_zqst;
    cudaGetSymbolAddress((void**)&p_res,  g_res);
    cudaGetSymbolAddress((void**)&p_ze,   g_ze);
    cudaGetSymbolAddress((void**)&p_zqst, g_zqst);

    k_copy_res<<<2048, 256>>>(z);

    for (int i = 0; i < NCB; i++) {
        const float* cb = cbs + (long)i * NK * ND;
        k_cbn<<<NK / 4, 128>>>(cb);
        // z_e = residual @ W_in[i] + b_in[i]
        k_gemm_ze<<<dim3(ND / 64, NB / 128), 256>>>(
            p_res, Wi + (long)i * NC * ND, bi + i * ND, p_ze, NC, ND);
        k_rownorm<<<NB / 4, 128>>>();
        // bf16 tensor dots + exact-rescore argmin
        k_dots<<<NB / 128, 256, DOT_SMEM_TOTAL>>>(cb);
        k_argsel<<<NB / 8, 256>>>(cb);
        k_gather<<<NB, 256>>>(cb, out, i, writeFull);
        // z_q_i = z_q_st @ W_out[i] + b_out[i], fused res/zq update
        k_gemm_out<<<dim3(NC / 64, NB / 128), 256>>>(
            p_zqst, Wo + (long)i * ND * NC, bo + i * NC, out, ND, NC, i);
    }

    k_loss<<<1, 1024>>>(out, writeFull);
}

// round 7
// speedup vs baseline: 1.7429x; 1.0061x over previous
#include <cuda_runtime.h>
#include <cuda_bf16.h>
#include <cstdint>

// Problem dims
#define NB 65536
#define NC 1024
#define ND 256
#define NK 2048
#define NCB 4

// Output layout (float32): [z_q][vq_loss][enc_loss][cbk_loss][codes][latents]
#define O_SC   (NB * NC)
#define O_CODE (O_SC + 3)
#define O_LAT  (O_CODE + NB * NCB)
#define O_TOT  (O_LAT + NB * NCB * ND)

// Scratch
__device__ float g_res[NB * NC];          // residual (256 MB)
__device__ float g_ze[NB * ND];           // z_e (64 MB)
__device__ float g_zqst[NB * ND];         // straight-through (64 MB)
__device__ float g_dot[(size_t)NB * NK];  // bf16 tensor dots (512 MB)
__device__ float g_cbn[NK];
__device__ float g_zn[NB];
__device__ int   g_idx[NB];
__device__ float g_rowloss[NB];

// bf16x2 pack: element order [a, b]
__device__ __forceinline__ uint32_t pack_bf16x2(float a, float b) {
    uint32_t r;
    asm("cvt.rn.satfinite.bf16x2.f32 %0, %1, %2;" : "=r"(r) : "f"(b), "f"(a));
    return r;
}

// ---- packed dual-fp32 FMA (Blackwell f32x2; per-lane bit-exact rn fp32) ----
__device__ __forceinline__ uint64_t pk2(float x, float y) {
    uint64_t r;
    asm("mov.b64 %0, {%1, %2};" : "=l"(r) : "f"(x), "f"(y));
    return r;
}
__device__ __forceinline__ void fma2(uint64_t& c, uint64_t a, uint64_t b) {
    asm("fma.rn.f32x2 %0, %1, %2, %0;" : "+l"(c) : "l"(a), "l"(b));
}
__device__ __forceinline__ float2 upk2(uint64_t v) {
    float2 f;
    asm("mov.b64 {%0, %1}, %2;" : "=f"(f.x), "=f"(f.y) : "l"(v));
    return f;
}

// ===========================================================================
__global__ void k_copy_res(const float* __restrict__ z) {
    int i = blockIdx.x * blockDim.x + threadIdx.x;
    int stride = gridDim.x * blockDim.x;
    const float4* src = (const float4*)z;
    float4* dst = (float4*)g_res;
    const int n4 = NB * NC / 4;
    for (int j = i; j < n4; j += stride) dst[j] = src[j];
}

// ===========================================================================
// fp32 GEMM body using packed FFMA2. Per-output arithmetic is the SAME
// ascending-k rn-fp32 FMA chain as the scalar version (bit-identical results);
// only the issue packing changes (two m-rows share one f32x2 instruction).
#define GEMM_BODY(A_, B_, K_, N_) \
    const int BM = 128, BN = 64, BK = 16, TM = 8, TN = 4; \
    __shared__ __align__(16) float As[BK][BM + 4]; \
    __shared__ __align__(16) float Bs[BK][BN]; \
    int tid = threadIdx.x; \
    int tx = tid & 15; \
    int ty = tid >> 4; \
    int row0 = blockIdx.y * BM; \
    int col0 = blockIdx.x * BN; \
    uint64_t accp[4][TN]; \
    _Pragma("unroll") for (int j = 0; j < 4; j++) \
        _Pragma("unroll") for (int n = 0; n < TN; n++) accp[j][n] = 0ull; \
    for (int k0 = 0; k0 < (K_); k0 += BK) { \
        _Pragma("unroll") for (int i = 0; i < 2; i++) { \
            int f4 = i * 256 + tid; \
            int r = f4 >> 2, c4 = f4 & 3; \
            float4 v = *(const float4*)&(A_)[(long)(row0 + r) * (K_) + k0 + c4 * 4]; \
            As[c4 * 4 + 0][r] = v.x; As[c4 * 4 + 1][r] = v.y; \
            As[c4 * 4 + 2][r] = v.z; As[c4 * 4 + 3][r] = v.w; \
        } \
        { \
            int r = tid >> 4, c4 = tid & 15; \
            float4 v = *(const float4*)&(B_)[(long)(k0 + r) * (N_) + col0 + c4 * 4]; \
            *(float4*)&Bs[r][c4 * 4] = v; \
        } \
        __syncthreads(); \
        _Pragma("unroll") for (int kk = 0; kk < BK; kk++) { \
            const uint64_t* ar = (const uint64_t*)&As[kk][ty * TM]; \
            uint64_t ap0 = ar[0], ap1 = ar[1], ap2 = ar[2], ap3 = ar[3]; \
            float4 b0 = *(const float4*)&Bs[kk][tx * TN]; \
            uint64_t bp0 = pk2(b0.x, b0.x); \
            uint64_t bp1 = pk2(b0.y, b0.y); \
            uint64_t bp2 = pk2(b0.z, b0.z); \
            uint64_t bp3 = pk2(b0.w, b0.w); \
            fma2(accp[0][0], ap0, bp0); fma2(accp[0][1], ap0, bp1); \
            fma2(accp[0][2], ap0, bp2); fma2(accp[0][3], ap0, bp3); \
            fma2(accp[1][0], ap1, bp0); fma2(accp[1][1], ap1, bp1); \
            fma2(accp[1][2], ap1, bp2); fma2(accp[1][3], ap1, bp3); \
            fma2(accp[2][0], ap2, bp0); fma2(accp[2][1], ap2, bp1); \
            fma2(accp[2][2], ap2, bp2); fma2(accp[2][3], ap2, bp3); \
            fma2(accp[3][0], ap3, bp0); fma2(accp[3][1], ap3, bp1); \
            fma2(accp[3][2], ap3, bp2); fma2(accp[3][3], ap3, bp3); \
        } \
        __syncthreads(); \
    }

// z_e = residual @ W_in + b_in
__global__ void __launch_bounds__(256) k_gemm_ze(
    const float* __restrict__ A, const float* __restrict__ Bm,
    const float* __restrict__ bias, float* __restrict__ C, int K_, int N_)
{
    GEMM_BODY(A, Bm, K_, N_)
#pragma unroll
    for (int j = 0; j < 4; j++) {
        long r0 = row0 + ty * TM + 2 * j;
#pragma unroll
        for (int n = 0; n < TN; n++) {
            int oc = col0 + tx * TN + n;
            float2 f = upk2(accp[j][n]);
            C[r0 * N_ + oc]       = __fadd_rn(f.x, bias[oc]);
            C[(r0 + 1) * N_ + oc] = __fadd_rn(f.y, bias[oc]);
        }
    }
}

// z_q_i = z_q_st @ W_out + b_out, fused apply: res -= qi, zq (+)= qi
__global__ void __launch_bounds__(256) k_gemm_out(
    const float* __restrict__ A, const float* __restrict__ Bm,
    const float* __restrict__ bias, float* __restrict__ zq,
    int K_, int N_, int cbi)
{
    GEMM_BODY(A, Bm, K_, N_)
#pragma unroll
    for (int j = 0; j < 4; j++) {
        long r0 = row0 + ty * TM + 2 * j;
#pragma unroll
        for (int n = 0; n < TN; n++) {
            int oc = col0 + tx * TN + n;
            float2 f = upk2(accp[j][n]);
            long off0 = r0 * N_ + oc;
            long off1 = (r0 + 1) * N_ + oc;
            float qi0 = __fadd_rn(f.x, bias[oc]);
            float qi1 = __fadd_rn(f.y, bias[oc]);
            g_res[off0] = __fsub_rn(g_res[off0], qi0);
            g_res[off1] = __fsub_rn(g_res[off1], qi1);
            zq[off0] = (cbi == 0) ? qi0 : __fadd_rn(zq[off0], qi0);
            zq[off1] = (cbi == 0) ? qi1 : __fadd_rn(zq[off1], qi1);
        }
    }
}

// ===========================================================================
// Row sum-of-squares (bit-identical to round-4 pass)
__device__ __forceinline__ float row_sumsq_vec4(const float* __restrict__ row) {
    int l = threadIdx.x & 31;
    float4 a = *(const float4*)&row[4 * l];
    float4 b = *(const float4*)&row[128 + 4 * l];
    float s;
    s = __fmul_rn(a.x, a.x);
    s = __fadd_rn(s, __fmul_rn(a.y, a.y));
    s = __fadd_rn(s, __fmul_rn(a.z, a.z));
    s = __fadd_rn(s, __fmul_rn(a.w, a.w));
    s = __fadd_rn(s, __fmul_rn(b.x, b.x));
    s = __fadd_rn(s, __fmul_rn(b.y, b.y));
    s = __fadd_rn(s, __fmul_rn(b.z, b.z));
    s = __fadd_rn(s, __fmul_rn(b.w, b.w));
#pragma unroll
    for (int off = 16; off > 0; off >>= 1)
        s = __fadd_rn(s, __shfl_down_sync(0xffffffffu, s, off));
    return s;
}

__global__ void k_cbn(const float* __restrict__ cb) {
    int w = threadIdx.x >> 5;
    int k = blockIdx.x * 4 + w;
    float s = row_sumsq_vec4(cb + (long)k * ND);
    if ((threadIdx.x & 31) == 0) g_cbn[k] = s;
}
__global__ void k_rownorm() {
    int w = threadIdx.x >> 5;
    int b = blockIdx.x * 4 + w;
    float s = row_sumsq_vec4(g_ze + (long)b * ND);
    if ((threadIdx.x & 31) == 0) g_zn[b] = s;
}

// ===========================================================================
// bf16 mma.sync dot GEMM: g_dot[row, code] = ze_bf16[row] . cb_bf16[code]
#define ASTRIDE 264
#define DOT_SMEM_A 0
#define DOT_SMEM_B (128 * ASTRIDE * 2)                 // 67584
#define DOT_SMEM_TOTAL (DOT_SMEM_B + 64 * ASTRIDE * 2) // 101376

__device__ __forceinline__ void mma16816(float* c, uint32_t a0, uint32_t a1,
                                         uint32_t a2, uint32_t a3,
                                         uint32_t b0, uint32_t b1) {
    asm volatile(
        "mma.sync.aligned.m16n8k16.row.col.f32.bf16.bf16.f32 "
        "{%0,%1,%2,%3}, {%4,%5,%6,%7}, {%8,%9}, {%0,%1,%2,%3};"
        : "+f"(c[0]), "+f"(c[1]), "+f"(c[2]), "+f"(c[3])
        : "r"(a0), "r"(a1), "r"(a2), "r"(a3), "r"(b0), "r"(b1));
}

__global__ void __launch_bounds__(256) k_dots(const float* __restrict__ cb) {
    extern __shared__ char smem[];
    __nv_bfloat16* As = (__nv_bfloat16*)(smem + DOT_SMEM_A);
    __nv_bfloat16* Bs = (__nv_bfloat16*)(smem + DOT_SMEM_B);
    int tid = threadIdx.x;
    int wid = tid >> 5, lane = tid & 31;
    int gid = lane >> 2, tig = lane & 3;
    int row0 = blockIdx.x * 128;

    for (int i = tid; i < 128 * 64; i += 256) {
        int r = i >> 6;
        int c = (i & 63) * 4;
        float4 v = *(const float4*)&g_ze[(long)(row0 + r) * ND + c];
        uint2 p = make_uint2(pack_bf16x2(v.x, v.y), pack_bf16x2(v.z, v.w));
        *(uint2*)&As[r * ASTRIDE + c] = p;
    }

    for (int chunk = 0; chunk < 32; chunk++) {
        int n0 = chunk * 64;
        for (int i = tid; i < 64 * 64; i += 256) {
            int r = i >> 6;
            int c = (i & 63) * 4;
            float4 v = *(const float4*)&cb[(long)(n0 + r) * ND + c];
            uint2 p = make_uint2(pack_bf16x2(v.x, v.y), pack_bf16x2(v.z, v.w));
            *(uint2*)&Bs[r * ASTRIDE + c] = p;
        }
        __syncthreads();

        float acc[8][4];
#pragma unroll
        for (int n8 = 0; n8 < 8; n8++)
#pragma unroll
            for (int j = 0; j < 4; j++) acc[n8][j] = 0.0f;

        int arow = wid * 16 + gid;
#pragma unroll
        for (int ks = 0; ks < 16; ks++) {
            int ak = ks * 16 + tig * 2;
            uint32_t a0 = *(const uint32_t*)&As[arow * ASTRIDE + ak];
            uint32_t a1 = *(const uint32_t*)&As[(arow + 8) * ASTRIDE + ak];
            uint32_t a2 = *(const uint32_t*)&As[arow * ASTRIDE + ak + 8];
            uint32_t a3 = *(const uint32_t*)&As[(arow + 8) * ASTRIDE + ak + 8];
#pragma unroll
            for (int n8 = 0; n8 < 8; n8++) {
                int brow = n8 * 8 + gid;
                uint32_t b0 = *(const uint32_t*)&Bs[brow * ASTRIDE + ak];
                uint32_t b1 = *(const uint32_t*)&Bs[brow * ASTRIDE + ak + 8];
                mma16816(acc[n8], a0, a1, a2, a3, b0, b1);
            }
        }

        size_t rbase0 = (size_t)(row0 + wid * 16 + gid) * NK + n0;
        size_t rbase1 = rbase0 + (size_t)8 * NK;
#pragma unroll
        for (int n8 = 0; n8 < 8; n8++) {
            int col = n8 * 8 + tig * 2;
            *(float2*)&g_dot[rbase0 + col] = make_float2(acc[n8][0], acc[n8][1]);
            *(float2*)&g_dot[rbase1 + col] = make_float2(acc[n8][2], acc[n8][3]);
        }
        __syncthreads();
    }
}

// ===========================================================================
// Approx argmin over bf16 dots + exact fp32 rescore within MARGIN.
#define MARGIN 0.12f
__global__ void __launch_bounds__(256) k_argsel(const float* __restrict__ cb) {
    int w = threadIdx.x >> 5, l = threadIdx.x & 31;
    int row = blockIdx.x * 8 + w;
    const float* drow = &g_dot[(size_t)row * NK];
    float zn = g_zn[row];

    float dmin = 3.4e38f;
#pragma unroll 4
    for (int j = 0; j < NK / 32; j++) {
        int k = j * 32 + l;
        float da = zn - 2.0f * drow[k] + g_cbn[k];
        dmin = fminf(dmin, da);
    }
#pragma unroll
    for (int off = 16; off > 0; off >>= 1)
        dmin = fminf(dmin, __shfl_xor_sync(0xffffffffu, dmin, off));
    float thr = dmin + MARGIN;

    float best = 3.4e38f;
    int bidx = 0x40000000;
    const float* ze = &g_ze[(long)row * ND];
    for (int j = 0; j < NK / 32; j++) {
        int k = j * 32 + l;
        float da = zn - 2.0f * drow[k] + g_cbn[k];
        if (da <= thr) {
            const float* cr = &cb[(long)k * ND];
            float acc = 0.0f;
#pragma unroll 8
            for (int t = 0; t < ND; t++) acc = fmaf(ze[t], cr[t], acc);
            float de = __fadd_rn(__fsub_rn(zn, __fmul_rn(2.0f, acc)), g_cbn[k]);
            if (de < best || (de == best && k < bidx)) { best = de; bidx = k; }
        }
    }
#pragma unroll
    for (int off = 16; off > 0; off >>= 1) {
        float ov = __shfl_down_sync(0xffffffffu, best, off);
        int   oi = __shfl_down_sync(0xffffffffu, bidx, off);
        if (ov < best || (ov == best && oi < bidx)) { best = ov; bidx = oi; }
    }
    if (l == 0) g_idx[row] = bidx;
}

// ===========================================================================
__global__ void k_gather(const float* __restrict__ cb, float* __restrict__ out,
                         int cbi, int writeFull) {
    int b = blockIdx.x;
    int t = threadIdx.x;
    int idx = g_idx[b];

    float ze = g_ze[(long)b * ND + t];
    float cv = cb[(long)idx * ND + t];
    g_zqst[(long)b * ND + t] = __fadd_rn(ze, __fsub_rn(cv, ze));

    float df = ze - cv;
    float s = df * df;
#pragma unroll
    for (int off = 16; off > 0; off >>= 1) s += __shfl_down_sync(0xffffffffu, s, off);
    __shared__ float ws[8];
    if ((t & 31) == 0) ws[t >> 5] = s;
    __syncthreads();
    if (t == 0) {
        float tot = 0.0f;
#pragma unroll
        for (int w = 0; w < 8; w++) tot += ws[w];
        g_rowloss[b] = (cbi == 0) ? tot : (g_rowloss[b] + tot);
    }

    if (writeFull) {
        out[O_LAT + (long)b * NC + cbi * ND + t] = ze;
        if (t == 0) out[O_CODE + (long)b * NCB + cbi] = (float)idx;
    }
}

// ===========================================================================
__global__ void k_loss(float* __restrict__ out, int writeFull) {
    __shared__ float sm[1024];
    int t = threadIdx.x;
    float s = 0.0f;
    for (int i = t; i < NB; i += 1024) s += g_rowloss[i];
    sm[t] = s;
    __syncthreads();
    for (int off = 512; off > 0; off >>= 1) {
        if (t < off) sm[t] += sm[t + off];
        __syncthreads();
    }
    if (t == 0 && writeFull) {
        float enc = 0.25f * sm[0] / 16777216.0f;
        out[O_SC + 0] = enc;
        out[O_SC + 1] = enc;
        out[O_SC + 2] = 0.0f;
    }
}

// ===========================================================================
extern "C" void kernel_launch(void* const* d_in, const int* in_sizes, int n_in,
                              void* d_out, int out_size) {
    const float* z   = (const float*)d_in[0];
    const float* cbs = (const float*)d_in[1];
    const float* Wi  = (const float*)d_in[2];
    const float* bi  = (const float*)d_in[3];
    const float* Wo  = (const float*)d_in[4];
    const float* bo  = (const float*)d_in[5];
    float* out = (float*)d_out;
    int writeFull = (out_size >= O_TOT) ? 1 : 0;

    cudaFuncSetAttribute(k_dots, cudaFuncAttributeMaxDynamicSharedMemorySize, DOT_SMEM_TOTAL);

    float *p_res, *p_ze, *p_zqst;
    cudaGetSymbolAddress((void**)&p_res,  g_res);
    cudaGetSymbolAddress((void**)&p_ze,   g_ze);
    cudaGetSymbolAddress((void**)&p_zqst, g_zqst);

    k_copy_res<<<2048, 256>>>(z);

    for (int i = 0; i < NCB; i++) {
        const float* cb = cbs + (long)i * NK * ND;
        k_cbn<<<NK / 4, 128>>>(cb);
        // z_e = residual @ W_in[i] + b_in[i]
        k_gemm_ze<<<dim3(ND / 64, NB / 128), 256>>>(
            p_res, Wi + (long)i * NC * ND, bi + i * ND, p_ze, NC, ND);
        k_rownorm<<<NB / 4, 128>>>();
        // bf16 tensor dots + exact-rescore argmin
        k_dots<<<NB / 128, 256, DOT_SMEM_TOTAL>>>(cb);
        k_argsel<<<NB / 8, 256>>>(cb);
        k_gather<<<NB, 256>>>(cb, out, i, writeFull);
        // z_q_i = z_q_st @ W_out[i] + b_out[i], fused res/zq update
        k_gemm_out<<<dim3(NC / 64, NB / 128), 256>>>(
            p_zqst, Wo + (long)i * ND * NC, bo + i * NC, out, ND, NC, i);
    }

    k_loss<<<1, 1024>>>(out, writeFull);
}

// round 9
// speedup vs baseline: 1.7945x; 1.0296x over previous
#include <cuda_runtime.h>
#include <cuda_bf16.h>
#include <cuda_fp16.h>
#include <cstdint>

// Problem dims
#define NB 65536
#define NC 1024
#define ND 256
#define NK 2048
#define NCB 4

// Output layout (float32): [z_q][vq_loss][enc_loss][cbk_loss][codes][latents]
#define O_SC   (NB * NC)
#define O_CODE (O_SC + 3)
#define O_LAT  (O_CODE + NB * NCB)
#define O_TOT  (O_LAT + NB * NCB * ND)

// Scratch
__device__ float g_res[NB * NC];            // residual (256 MB)
__device__ float g_ze[NB * ND];             // z_e (64 MB)
__device__ float g_zqst[NB * ND];           // straight-through (64 MB)
__device__ __half g_dot[(size_t)NB * NK];   // fp16 tensor dots (256 MB)
__device__ float g_cbn[NK];
__device__ float g_zn[NB];
__device__ int   g_idx[NB];
__device__ float g_rowloss[NB];

// bf16x2 pack: element order [a, b]
__device__ __forceinline__ uint32_t pack_bf16x2(float a, float b) {
    uint32_t r;
    asm("cvt.rn.satfinite.bf16x2.f32 %0, %1, %2;" : "=r"(r) : "f"(b), "f"(a));
    return r;
}

// ===========================================================================
// fp32 SIMT GEMM body (bit-identical arithmetic to round-4/6/7 passing path)
#define GEMM_BODY(A_, B_, K_, N_) \
    const int BM = 128, BN = 64, BK = 16, TM = 8, TN = 4; \
    __shared__ float As[BK][BM + 4]; \
    __shared__ float Bs[BK][BN]; \
    int tid = threadIdx.x; \
    int tx = tid & 15; \
    int ty = tid >> 4; \
    int row0 = blockIdx.y * BM; \
    int col0 = blockIdx.x * BN; \
    float acc[TM][TN]; \
    _Pragma("unroll") for (int m = 0; m < TM; m++) \
        _Pragma("unroll") for (int n = 0; n < TN; n++) acc[m][n] = 0.0f; \
    for (int k0 = 0; k0 < (K_); k0 += BK) { \
        _Pragma("unroll") for (int i = 0; i < 2; i++) { \
            int f4 = i * 256 + tid; \
            int r = f4 >> 2, c4 = f4 & 3; \
            float4 v = *(const float4*)&(A_)[(long)(row0 + r) * (K_) + k0 + c4 * 4]; \
            As[c4 * 4 + 0][r] = v.x; As[c4 * 4 + 1][r] = v.y; \
            As[c4 * 4 + 2][r] = v.z; As[c4 * 4 + 3][r] = v.w; \
        } \
        { \
            int r = tid >> 4, c4 = tid & 15; \
            float4 v = *(const float4*)&(B_)[(long)(k0 + r) * (N_) + col0 + c4 * 4]; \
            *(float4*)&Bs[r][c4 * 4] = v; \
        } \
        __syncthreads(); \
        _Pragma("unroll") for (int kk = 0; kk < BK; kk++) { \
            float a[TM], b[TN]; \
            float4 a0 = *(const float4*)&As[kk][ty * TM]; \
            float4 a1 = *(const float4*)&As[kk][ty * TM + 4]; \
            a[0]=a0.x; a[1]=a0.y; a[2]=a0.z; a[3]=a0.w; \
            a[4]=a1.x; a[5]=a1.y; a[6]=a1.z; a[7]=a1.w; \
            float4 b0 = *(const float4*)&Bs[kk][tx * TN]; \
            b[0]=b0.x; b[1]=b0.y; b[2]=b0.z; b[3]=b0.w; \
            _Pragma("unroll") for (int m = 0; m < TM; m++) \
                _Pragma("unroll") for (int n = 0; n < TN; n++) \
                    acc[m][n] = fmaf(a[m], b[n], acc[m][n]); \
        } \
        __syncthreads(); \
    }

// z_e = A @ W_in + b_in
__global__ void __launch_bounds__(256) k_gemm_ze(
    const float* __restrict__ A, const float* __restrict__ Bm,
    const float* __restrict__ bias, float* __restrict__ C, int K_, int N_)
{
    GEMM_BODY(A, Bm, K_, N_)
#pragma unroll
    for (int m = 0; m < TM; m++) {
        long orow = row0 + ty * TM + m;
#pragma unroll
        for (int n = 0; n < TN; n++) {
            int oc = col0 + tx * TN + n;
            C[orow * N_ + oc] = __fadd_rn(acc[m][n], bias[oc]);
        }
    }
}

// z_q_i = z_q_st @ W_out + b_out, fused apply:
//  cbi==0     : res = z - qi      ; zq = qi
//  0<cbi<NCB-1: res = res - qi    ; zq += qi
//  cbi==NCB-1 : (res dead, skip)  ; zq += qi
__global__ void __launch_bounds__(256) k_gemm_out(
    const float* __restrict__ A, const float* __restrict__ Bm,
    const float* __restrict__ bias, float* __restrict__ zq,
    const float* __restrict__ z, int K_, int N_, int cbi)
{
    GEMM_BODY(A, Bm, K_, N_)
#pragma unroll
    for (int m = 0; m < TM; m++) {
        long orow = row0 + ty * TM + m;
#pragma unroll
        for (int n = 0; n < TN; n++) {
            int oc = col0 + tx * TN + n;
            long off = orow * N_ + oc;
            float qi = __fadd_rn(acc[m][n], bias[oc]);
            if (cbi == 0) {
                g_res[off] = __fsub_rn(z[off], qi);
                zq[off] = qi;
            } else if (cbi < NCB - 1) {
                g_res[off] = __fsub_rn(g_res[off], qi);
                zq[off] = __fadd_rn(zq[off], qi);
            } else {
                zq[off] = __fadd_rn(zq[off], qi);
            }
        }
    }
}

// ===========================================================================
// Row sum-of-squares (bit-identical to round-4 pass)
__device__ __forceinline__ float row_sumsq_vec4(const float* __restrict__ row) {
    int l = threadIdx.x & 31;
    float4 a = *(const float4*)&row[4 * l];
    float4 b = *(const float4*)&row[128 + 4 * l];
    float s;
    s = __fmul_rn(a.x, a.x);
    s = __fadd_rn(s, __fmul_rn(a.y, a.y));
    s = __fadd_rn(s, __fmul_rn(a.z, a.z));
    s = __fadd_rn(s, __fmul_rn(a.w, a.w));
    s = __fadd_rn(s, __fmul_rn(b.x, b.x));
    s = __fadd_rn(s, __fmul_rn(b.y, b.y));
    s = __fadd_rn(s, __fmul_rn(b.z, b.z));
    s = __fadd_rn(s, __fmul_rn(b.w, b.w));
#pragma unroll
    for (int off = 16; off > 0; off >>= 1)
        s = __fadd_rn(s, __shfl_down_sync(0xffffffffu, s, off));
    return s;
}

__global__ void k_cbn(const float* __restrict__ cb) {
    int w = threadIdx.x >> 5;
    int k = blockIdx.x * 4 + w;
    float s = row_sumsq_vec4(cb + (long)k * ND);
    if ((threadIdx.x & 31) == 0) g_cbn[k] = s;
}
__global__ void k_rownorm() {
    int w = threadIdx.x >> 5;
    int b = blockIdx.x * 4 + w;
    float s = row_sumsq_vec4(g_ze + (long)b * ND);
    if ((threadIdx.x & 31) == 0) g_zn[b] = s;
}

// ===========================================================================
// bf16 mma.sync dot GEMM: g_dot[row, code] = ze_bf16[row] . cb_bf16[code] (fp16 store)
#define ASTRIDE 264
#define DOT_SMEM_B (128 * ASTRIDE * 2)                 // 67584
#define DOT_SMEM_TOTAL (DOT_SMEM_B + 64 * ASTRIDE * 2) // 101376

__device__ __forceinline__ void mma16816(float* c, uint32_t a0, uint32_t a1,
                                         uint32_t a2, uint32_t a3,
                                         uint32_t b0, uint32_t b1) {
    asm volatile(
        "mma.sync.aligned.m16n8k16.row.col.f32.bf16.bf16.f32 "
        "{%0,%1,%2,%3}, {%4,%5,%6,%7}, {%8,%9}, {%0,%1,%2,%3};"
        : "+f"(c[0]), "+f"(c[1]), "+f"(c[2]), "+f"(c[3])
        : "r"(a0), "r"(a1), "r"(a2), "r"(a3), "r"(b0), "r"(b1));
}

__global__ void __launch_bounds__(256) k_dots(const float* __restrict__ cb) {
    extern __shared__ char smem[];
    __nv_bfloat16* As = (__nv_bfloat16*)(smem);
    __nv_bfloat16* Bs = (__nv_bfloat16*)(smem + DOT_SMEM_B);
    int tid = threadIdx.x;
    int wid = tid >> 5, lane = tid & 31;
    int gid = lane >> 2, tig = lane & 3;
    int row0 = blockIdx.x * 128;

    for (int i = tid; i < 128 * 64; i += 256) {
        int r = i >> 6;
        int c = (i & 63) * 4;
        float4 v = *(const float4*)&g_ze[(long)(row0 + r) * ND + c];
        uint2 p = make_uint2(pack_bf16x2(v.x, v.y), pack_bf16x2(v.z, v.w));
        *(uint2*)&As[r * ASTRIDE + c] = p;
    }

    for (int chunk = 0; chunk < 32; chunk++) {
        int n0 = chunk * 64;
        for (int i = tid; i < 64 * 64; i += 256) {
            int r = i >> 6;
            int c = (i & 63) * 4;
            float4 v = *(const float4*)&cb[(long)(n0 + r) * ND + c];
            uint2 p = make_uint2(pack_bf16x2(v.x, v.y), pack_bf16x2(v.z, v.w));
            *(uint2*)&Bs[r * ASTRIDE + c] = p;
        }
        __syncthreads();

        float acc[8][4];
#pragma unroll
        for (int n8 = 0; n8 < 8; n8++)
#pragma unroll
            for (int j = 0; j < 4; j++) acc[n8][j] = 0.0f;

        int arow = wid * 16 + gid;
#pragma unroll
        for (int ks = 0; ks < 16; ks++) {
            int ak = ks * 16 + tig * 2;
            uint32_t a0 = *(const uint32_t*)&As[arow * ASTRIDE + ak];
            uint32_t a1 = *(const uint32_t*)&As[(arow + 8) * ASTRIDE + ak];
            uint32_t a2 = *(const uint32_t*)&As[arow * ASTRIDE + ak + 8];
            uint32_t a3 = *(const uint32_t*)&As[(arow + 8) * ASTRIDE + ak + 8];
#pragma unroll
            for (int n8 = 0; n8 < 8; n8++) {
                int brow = n8 * 8 + gid;
                uint32_t b0 = *(const uint32_t*)&Bs[brow * ASTRIDE + ak];
                uint32_t b1 = *(const uint32_t*)&Bs[brow * ASTRIDE + ak + 8];
                mma16816(acc[n8], a0, a1, a2, a3, b0, b1);
            }
        }

        // fp16 store: lane holds D[r][tig*2,+1] and D[r+8][tig*2,+1]
        size_t rbase0 = (size_t)(row0 + wid * 16 + gid) * NK + n0;
        size_t rbase1 = rbase0 + (size_t)8 * NK;
#pragma unroll
        for (int n8 = 0; n8 < 8; n8++) {
            int col = n8 * 8 + tig * 2;
            *(__half2*)&g_dot[rbase0 + col] = __floats2half2_rn(acc[n8][0], acc[n8][1]);
            *(__half2*)&g_dot[rbase1 + col] = __floats2half2_rn(acc[n8][2], acc[n8][3]);
        }
        __syncthreads();
    }
}

// ===========================================================================
// Approx argmin over fp16 dots + exact fp32 rescore within MARGIN.
// fp16+bf16 combined approx error << MARGIN, so the true argmin is always in
// the candidate set; the exact rescore chain is bit-identical to round-4.
#define MARGIN 0.12f
__global__ void __launch_bounds__(256) k_argsel(const float* __restrict__ cb) {
    int w = threadIdx.x >> 5, l = threadIdx.x & 31;
    int row = blockIdx.x * 8 + w;
    const __half2* drow = (const __half2*)&g_dot[(size_t)row * NK];
    float zn = g_zn[row];

    float dmin = 3.4e38f;
#pragma unroll 4
    for (int j = 0; j < NK / 64; j++) {
        int kh = j * 32 + l;               // half2 index -> codes 2kh, 2kh+1
        float2 dd = __half22float2(drow[kh]);
        float da0 = zn - 2.0f * dd.x + g_cbn[2 * kh];
        float da1 = zn - 2.0f * dd.y + g_cbn[2 * kh + 1];
        dmin = fminf(dmin, fminf(da0, da1));
    }
#pragma unroll
    for (int off = 16; off > 0; off >>= 1)
        dmin = fminf(dmin, __shfl_xor_sync(0xffffffffu, dmin, off));
    float thr = dmin + MARGIN;

    float best = 3.4e38f;
    int bidx = 0x40000000;
    const float* ze = &g_ze[(long)row * ND];
    for (int j = 0; j < NK / 64; j++) {
        int kh = j * 32 + l;
        float2 dd = __half22float2(drow[kh]);
#pragma unroll
        for (int h = 0; h < 2; h++) {
            int k = 2 * kh + h;
            float da = zn - 2.0f * (h ? dd.y : dd.x) + g_cbn[k];
            if (da <= thr) {
                const float* cr = &cb[(long)k * ND];
                float acc = 0.0f;
#pragma unroll 8
                for (int t = 0; t < ND; t++) acc = fmaf(ze[t], cr[t], acc);
                float de = __fadd_rn(__fsub_rn(zn, __fmul_rn(2.0f, acc)), g_cbn[k]);
                if (de < best || (de == best && k < bidx)) { best = de; bidx = k; }
            }
        }
    }
#pragma unroll
    for (int off = 16; off > 0; off >>= 1) {
        float ov = __shfl_down_sync(0xffffffffu, best, off);
        int   oi = __shfl_down_sync(0xffffffffu, bidx, off);
        if (ov < best || (ov == best && oi < bidx)) { best = ov; bidx = oi; }
    }
    if (l == 0) g_idx[row] = bidx;
}

// ===========================================================================
__global__ void k_gather(const float* __restrict__ cb, float* __restrict__ out,
                         int cbi, int writeFull) {
    int b = blockIdx.x;
    int t = threadIdx.x;
    int idx = g_idx[b];

    float ze = g_ze[(long)b * ND + t];
    float cv = cb[(long)idx * ND + t];
    g_zqst[(long)b * ND + t] = __fadd_rn(ze, __fsub_rn(cv, ze));

    float df = ze - cv;
    float s = df * df;
#pragma unroll
    for (int off = 16; off > 0; off >>= 1) s += __shfl_down_sync(0xffffffffu, s, off);
    __shared__ float ws[8];
    if ((t & 31) == 0) ws[t >> 5] = s;
    __syncthreads();
    if (t == 0) {
        float tot = 0.0f;
#pragma unroll
        for (int w = 0; w < 8; w++) tot += ws[w];
        g_rowloss[b] = (cbi == 0) ? tot : (g_rowloss[b] + tot);
    }

    if (writeFull) {
        out[O_LAT + (long)b * NC + cbi * ND + t] = ze;
        if (t == 0) out[O_CODE + (long)b * NCB + cbi] = (float)idx;
    }
}

// ===========================================================================
__global__ void k_loss(float* __restrict__ out, int writeFull) {
    __shared__ float sm[1024];
    int t = threadIdx.x;
    float s = 0.0f;
    for (int i = t; i < NB; i += 1024) s += g_rowloss[i];
    sm[t] = s;
    __syncthreads();
    for (int off = 512; off > 0; off >>= 1) {
        if (t < off) sm[t] += sm[t + off];
        __syncthreads();
    }
    if (t == 0 && writeFull) {
        float enc = 0.25f * sm[0] / 16777216.0f;
        out[O_SC + 0] = enc;
        out[O_SC + 1] = enc;
        out[O_SC + 2] = 0.0f;
    }
}

// ===========================================================================
extern "C" void kernel_launch(void* const* d_in, const int* in_sizes, int n_in,
                              void* d_out, int out_size) {
    const float* z   = (const float*)d_in[0];
    const float* cbs = (const float*)d_in[1];
    const float* Wi  = (const float*)d_in[2];
    const float* bi  = (const float*)d_in[3];
    const float* Wo  = (const float*)d_in[4];
    const float* bo  = (const float*)d_in[5];
    float* out = (float*)d_out;
    int writeFull = (out_size >= O_TOT) ? 1 : 0;

    cudaFuncSetAttribute(k_dots, cudaFuncAttributeMaxDynamicSharedMemorySize, DOT_SMEM_TOTAL);

    float *p_res, *p_ze, *p_zqst;
    cudaGetSymbolAddress((void**)&p_res,  g_res);
    cudaGetSymbolAddress((void**)&p_ze,   g_ze);
    cudaGetSymbolAddress((void**)&p_zqst, g_zqst);

    for (int i = 0; i < NCB; i++) {
        const float* cb = cbs + (long)i * NK * ND;
        k_cbn<<<NK / 4, 128>>>(cb);
        // z_e = residual @ W_in[i] + b_in[i]  (codebook 0 reads z directly)
        const float* Ain = (i == 0) ? z : p_res;
        k_gemm_ze<<<dim3(ND / 64, NB / 128), 256>>>(
            Ain, Wi + (long)i * NC * ND, bi + i * ND, p_ze, NC, ND);
        k_rownorm<<<NB / 4, 128>>>();
        // bf16 tensor dots (fp16 store) + exact-rescore argmin
        k_dots<<<NB / 128, 256, DOT_SMEM_TOTAL>>>(cb);
        k_argsel<<<NB / 8, 256>>>(cb);
        k_gather<<<NB, 256>>>(cb, out, i, writeFull);
        // z_q_i = z_q_st @ W_out[i] + b_out[i], fused res/zq update
        k_gemm_out<<<dim3(NC / 64, NB / 128), 256>>>(
            p_zqst, Wo + (long)i * ND * NC, bo + i * NC, out, z, ND, NC, i);
    }

    k_loss<<<1, 1024>>>(out, writeFull);
}

// round 11
// speedup vs baseline: 1.8714x; 1.0428x over previous
#include <cuda_runtime.h>
#include <cuda_bf16.h>
#include <cuda_fp16.h>
#include <cstdint>

// Problem dims
#define NB 65536
#define NBH (NB / 2)
#define NC 1024
#define ND 256
#define NK 2048
#define NCB 4

// Output layout (float32): [z_q][vq_loss][enc_loss][cbk_loss][codes][latents]
#define O_SC   (NB * NC)
#define O_CODE (O_SC + 3)
#define O_LAT  (O_CODE + NB * NCB)
#define O_TOT  (O_LAT + NB * NCB * ND)

// Scratch
__device__ float g_res[NB * NC];            // residual (256 MB)
__device__ float g_ze[NB * ND];             // z_e (64 MB)
__device__ float g_zqst[NB * ND];           // straight-through (64 MB)
__device__ __half g_dot[(size_t)NB * NK];   // fp16 tensor dots (256 MB)
__device__ float g_cbn[NCB * NK];           // per-codebook ||cb_k||^2 (race-free)
__device__ float g_zn[NB];
__device__ int   g_idx[NB];
__device__ float g_rowloss[NB];

// bf16x2 pack: element order [a, b]
__device__ __forceinline__ uint32_t pack_bf16x2(float a, float b) {
    uint32_t r;
    asm("cvt.rn.satfinite.bf16x2.f32 %0, %1, %2;" : "=r"(r) : "f"(b), "f"(a));
    return r;
}

// ===========================================================================
// fp32 SIMT GEMM body (bit-identical arithmetic to passing rounds; absolute
// row indexing via rbase so half-batch launches do identical per-row work)
#define GEMM_BODY(A_, B_, K_, N_) \
    const int BM = 128, BN = 64, BK = 16, TM = 8, TN = 4; \
    __shared__ float As[BK][BM + 4]; \
    __shared__ float Bs[BK][BN]; \
    int tid = threadIdx.x; \
    int tx = tid & 15; \
    int ty = tid >> 4; \
    int row0 = blockIdx.y * BM + rbase; \
    int col0 = blockIdx.x * BN; \
    float acc[TM][TN]; \
    _Pragma("unroll") for (int m = 0; m < TM; m++) \
        _Pragma("unroll") for (int n = 0; n < TN; n++) acc[m][n] = 0.0f; \
    for (int k0 = 0; k0 < (K_); k0 += BK) { \
        _Pragma("unroll") for (int i = 0; i < 2; i++) { \
            int f4 = i * 256 + tid; \
            int r = f4 >> 2, c4 = f4 & 3; \
            float4 v = *(const float4*)&(A_)[(long)(row0 + r) * (K_) + k0 + c4 * 4]; \
            As[c4 * 4 + 0][r] = v.x; As[c4 * 4 + 1][r] = v.y; \
            As[c4 * 4 + 2][r] = v.z; As[c4 * 4 + 3][r] = v.w; \
        } \
        { \
            int r = tid >> 4, c4 = tid & 15; \
            float4 v = *(const float4*)&(B_)[(long)(k0 + r) * (N_) + col0 + c4 * 4]; \
            *(float4*)&Bs[r][c4 * 4] = v; \
        } \
        __syncthreads(); \
        _Pragma("unroll") for (int kk = 0; kk < BK; kk++) { \
            float a[TM], b[TN]; \
            float4 a0 = *(const float4*)&As[kk][ty * TM]; \
            float4 a1 = *(const float4*)&As[kk][ty * TM + 4]; \
            a[0]=a0.x; a[1]=a0.y; a[2]=a0.z; a[3]=a0.w; \
            a[4]=a1.x; a[5]=a1.y; a[6]=a1.z; a[7]=a1.w; \
            float4 b0 = *(const float4*)&Bs[kk][tx * TN]; \
            b[0]=b0.x; b[1]=b0.y; b[2]=b0.z; b[3]=b0.w; \
            _Pragma("unroll") for (int m = 0; m < TM; m++) \
                _Pragma("unroll") for (int n = 0; n < TN; n++) \
                    acc[m][n] = fmaf(a[m], b[n], acc[m][n]); \
        } \
        __syncthreads(); \
    }

// z_e = A @ W_in + b_in
__global__ void __launch_bounds__(256) k_gemm_ze(
    const float* __restrict__ A, const float* __restrict__ Bm,
    const float* __restrict__ bias, float* __restrict__ C,
    int K_, int N_, int rbase)
{
    GEMM_BODY(A, Bm, K_, N_)
#pragma unroll
    for (int m = 0; m < TM; m++) {
        long orow = row0 + ty * TM + m;
#pragma unroll
        for (int n = 0; n < TN; n++) {
            int oc = col0 + tx * TN + n;
            C[orow * N_ + oc] = __fadd_rn(acc[m][n], bias[oc]);
        }
    }
}

// z_q_i = z_q_st @ W_out + b_out, fused apply:
//  cbi==0     : res = z - qi      ; zq = qi
//  0<cbi<NCB-1: res = res - qi    ; zq += qi
//  cbi==NCB-1 : (res dead, skip)  ; zq += qi
__global__ void __launch_bounds__(256) k_gemm_out(
    const float* __restrict__ A, const float* __restrict__ Bm,
    const float* __restrict__ bias, float* __restrict__ zq,
    const float* __restrict__ z, int K_, int N_, int cbi, int rbase)
{
    GEMM_BODY(A, Bm, K_, N_)
#pragma unroll
    for (int m = 0; m < TM; m++) {
        long orow = row0 + ty * TM + m;
#pragma unroll
        for (int n = 0; n < TN; n++) {
            int oc = col0 + tx * TN + n;
            long off = orow * N_ + oc;
            float qi = __fadd_rn(acc[m][n], bias[oc]);
            if (cbi == 0) {
                g_res[off] = __fsub_rn(z[off], qi);
                zq[off] = qi;
            } else if (cbi < NCB - 1) {
                g_res[off] = __fsub_rn(g_res[off], qi);
                zq[off] = __fadd_rn(zq[off], qi);
            } else {
                zq[off] = __fadd_rn(zq[off], qi);
            }
        }
    }
}

// ===========================================================================
// Row sum-of-squares (bit-identical to passing rounds)
__device__ __forceinline__ float row_sumsq_vec4(const float* __restrict__ row) {
    int l = threadIdx.x & 31;
    float4 a = *(const float4*)&row[4 * l];
    float4 b = *(const float4*)&row[128 + 4 * l];
    float s;
    s = __fmul_rn(a.x, a.x);
    s = __fadd_rn(s, __fmul_rn(a.y, a.y));
    s = __fadd_rn(s, __fmul_rn(a.z, a.z));
    s = __fadd_rn(s, __fmul_rn(a.w, a.w));
    s = __fadd_rn(s, __fmul_rn(b.x, b.x));
    s = __fadd_rn(s, __fmul_rn(b.y, b.y));
    s = __fadd_rn(s, __fmul_rn(b.z, b.z));
    s = __fadd_rn(s, __fmul_rn(b.w, b.w));
#pragma unroll
    for (int off = 16; off > 0; off >>= 1)
        s = __fadd_rn(s, __shfl_down_sync(0xffffffffu, s, off));
    return s;
}

// ||cb_k||^2 for codebook cbi -> g_cbn[cbi*NK + k]
__global__ void k_cbn(const float* __restrict__ cb, int cbi) {
    int w = threadIdx.x >> 5;
    int k = blockIdx.x * 4 + w;
    float s = row_sumsq_vec4(cb + (long)k * ND);
    if ((threadIdx.x & 31) == 0) g_cbn[cbi * NK + k] = s;
}
__global__ void k_rownorm(int rbase) {
    int w = threadIdx.x >> 5;
    int b = blockIdx.x * 4 + w + rbase;
    float s = row_sumsq_vec4(g_ze + (long)b * ND);
    if ((threadIdx.x & 31) == 0) g_zn[b] = s;
}

// ===========================================================================
// bf16 mma.sync dot GEMM: g_dot[row, code] = ze_bf16[row] . cb_bf16[code] (fp16 store)
#define ASTRIDE 264
#define DOT_SMEM_B (128 * ASTRIDE * 2)                 // 67584
#define DOT_SMEM_TOTAL (DOT_SMEM_B + 64 * ASTRIDE * 2) // 101376

__device__ __forceinline__ void mma16816(float* c, uint32_t a0, uint32_t a1,
                                         uint32_t a2, uint32_t a3,
                                         uint32_t b0, uint32_t b1) {
    asm volatile(
        "mma.sync.aligned.m16n8k16.row.col.f32.bf16.bf16.f32 "
        "{%0,%1,%2,%3}, {%4,%5,%6,%7}, {%8,%9}, {%0,%1,%2,%3};"
        : "+f"(c[0]), "+f"(c[1]), "+f"(c[2]), "+f"(c[3])
        : "r"(a0), "r"(a1), "r"(a2), "r"(a3), "r"(b0), "r"(b1));
}

__global__ void __launch_bounds__(256) k_dots(const float* __restrict__ cb, int rbase) {
    extern __shared__ char smem[];
    __nv_bfloat16* As = (__nv_bfloat16*)(smem);
    __nv_bfloat16* Bs = (__nv_bfloat16*)(smem + DOT_SMEM_B);
    int tid = threadIdx.x;
    int wid = tid >> 5, lane = tid & 31;
    int gid = lane >> 2, tig = lane & 3;
    int row0 = blockIdx.x * 128 + rbase;

    for (int i = tid; i < 128 * 64; i += 256) {
        int r = i >> 6;
        int c = (i & 63) * 4;
        float4 v = *(const float4*)&g_ze[(long)(row0 + r) * ND + c];
        uint2 p = make_uint2(pack_bf16x2(v.x, v.y), pack_bf16x2(v.z, v.w));
        *(uint2*)&As[r * ASTRIDE + c] = p;
    }

    for (int chunk = 0; chunk < 32; chunk++) {
        int n0 = chunk * 64;
        for (int i = tid; i < 64 * 64; i += 256) {
            int r = i >> 6;
            int c = (i & 63) * 4;
            float4 v = *(const float4*)&cb[(long)(n0 + r) * ND + c];
            uint2 p = make_uint2(pack_bf16x2(v.x, v.y), pack_bf16x2(v.z, v.w));
            *(uint2*)&Bs[r * ASTRIDE + c] = p;
        }
        __syncthreads();

        float acc[8][4];
#pragma unroll
        for (int n8 = 0; n8 < 8; n8++)
#pragma unroll
            for (int j = 0; j < 4; j++) acc[n8][j] = 0.0f;

        int arow = wid * 16 + gid;
#pragma unroll
        for (int ks = 0; ks < 16; ks++) {
            int ak = ks * 16 + tig * 2;
            uint32_t a0 = *(const uint32_t*)&As[arow * ASTRIDE + ak];
            uint32_t a1 = *(const uint32_t*)&As[(arow + 8) * ASTRIDE + ak];
            uint32_t a2 = *(const uint32_t*)&As[arow * ASTRIDE + ak + 8];
            uint32_t a3 = *(const uint32_t*)&As[(arow + 8) * ASTRIDE + ak + 8];
#pragma unroll
            for (int n8 = 0; n8 < 8; n8++) {
                int brow = n8 * 8 + gid;
                uint32_t b0 = *(const uint32_t*)&Bs[brow * ASTRIDE + ak];
                uint32_t b1 = *(const uint32_t*)&Bs[brow * ASTRIDE + ak + 8];
                mma16816(acc[n8], a0, a1, a2, a3, b0, b1);
            }
        }

        size_t rbase0 = (size_t)(row0 + wid * 16 + gid) * NK + n0;
        size_t rbase1 = rbase0 + (size_t)8 * NK;
#pragma unroll
        for (int n8 = 0; n8 < 8; n8++) {
            int col = n8 * 8 + tig * 2;
            *(__half2*)&g_dot[rbase0 + col] = __floats2half2_rn(acc[n8][0], acc[n8][1]);
            *(__half2*)&g_dot[rbase1 + col] = __floats2half2_rn(acc[n8][2], acc[n8][3]);
        }
        __syncthreads();
    }
}

// ===========================================================================
// Approx argmin over fp16 dots + exact fp32 rescore within MARGIN.
#define MARGIN 0.12f
__global__ void __launch_bounds__(256) k_argsel(const float* __restrict__ cb,
                                                int cbi, int rbase) {
    int w = threadIdx.x >> 5, l = threadIdx.x & 31;
    int row = blockIdx.x * 8 + w + rbase;
    const __half2* drow = (const __half2*)&g_dot[(size_t)row * NK];
    const float* cbn = &g_cbn[cbi * NK];
    float zn = g_zn[row];

    float dmin = 3.4e38f;
#pragma unroll 4
    for (int j = 0; j < NK / 64; j++) {
        int kh = j * 32 + l;
        float2 dd = __half22float2(drow[kh]);
        float da0 = zn - 2.0f * dd.x + cbn[2 * kh];
        float da1 = zn - 2.0f * dd.y + cbn[2 * kh + 1];
        dmin = fminf(dmin, fminf(da0, da1));
    }
#pragma unroll
    for (int off = 16; off > 0; off >>= 1)
        dmin = fminf(dmin, __shfl_xor_sync(0xffffffffu, dmin, off));
    float thr = dmin + MARGIN;

    float best = 3.4e38f;
    int bidx = 0x40000000;
    const float* ze = &g_ze[(long)row * ND];
    for (int j = 0; j < NK / 64; j++) {
        int kh = j * 32 + l;
        float2 dd = __half22float2(drow[kh]);
#pragma unroll
        for (int h = 0; h < 2; h++) {
            int k = 2 * kh + h;
            float da = zn - 2.0f * (h ? dd.y : dd.x) + cbn[k];
            if (da <= thr) {
                const float* cr = &cb[(long)k * ND];
                float acc = 0.0f;
#pragma unroll 8
                for (int t = 0; t < ND; t++) acc = fmaf(ze[t], cr[t], acc);
                float de = __fadd_rn(__fsub_rn(zn, __fmul_rn(2.0f, acc)), cbn[k]);
                if (de < best || (de == best && k < bidx)) { best = de; bidx = k; }
            }
        }
    }
#pragma unroll
    for (int off = 16; off > 0; off >>= 1) {
        float ov = __shfl_down_sync(0xffffffffu, best, off);
        int   oi = __shfl_down_sync(0xffffffffu, bidx, off);
        if (ov < best || (ov == best && oi < bidx)) { best = ov; bidx = oi; }
    }
    if (l == 0) g_idx[row] = bidx;
}

// ===========================================================================
__global__ void k_gather(const float* __restrict__ cb, float* __restrict__ out,
                         int cbi, int writeFull, int rbase) {
    int b = blockIdx.x + rbase;
    int t = threadIdx.x;
    int idx = g_idx[b];

    float ze = g_ze[(long)b * ND + t];
    float cv = cb[(long)idx * ND + t];
    g_zqst[(long)b * ND + t] = __fadd_rn(ze, __fsub_rn(cv, ze));

    float df = ze - cv;
    float s = df * df;
#pragma unroll
    for (int off = 16; off > 0; off >>= 1) s += __shfl_down_sync(0xffffffffu, s, off);
    __shared__ float ws[8];
    if ((t & 31) == 0) ws[t >> 5] = s;
    __syncthreads();
    if (t == 0) {
        float tot = 0.0f;
#pragma unroll
        for (int w = 0; w < 8; w++) tot += ws[w];
        g_rowloss[b] = (cbi == 0) ? tot : (g_rowloss[b] + tot);
    }

    if (writeFull) {
        out[O_LAT + (long)b * NC + cbi * ND + t] = ze;
        if (t == 0) out[O_CODE + (long)b * NCB + cbi] = (float)idx;
    }
}

// ===========================================================================
__global__ void k_loss(float* __restrict__ out, int writeFull) {
    __shared__ float sm[1024];
    int t = threadIdx.x;
    float s = 0.0f;
    for (int i = t; i < NB; i += 1024) s += g_rowloss[i];
    sm[t] = s;
    __syncthreads();
    for (int off = 512; off > 0; off >>= 1) {
        if (t < off) sm[t] += sm[t + off];
        __syncthreads();
    }
    if (t == 0 && writeFull) {
        float enc = 0.25f * sm[0] / 16777216.0f;
        out[O_SC + 0] = enc;
        out[O_SC + 1] = enc;
        out[O_SC + 2] = 0.0f;
    }
}

// ===========================================================================
static void run_half(cudaStream_t st, int rbase,
                     const float* z, const float* cbs,
                     const float* Wi, const float* bi,
                     const float* Wo, const float* bo,
                     float* out, int writeFull,
                     float* p_res, float* p_ze, float* p_zqst)
{
    for (int i = 0; i < NCB; i++) {
        const float* cb = cbs + (long)i * NK * ND;
        const float* Ain = (i == 0) ? z : p_res;
        k_gemm_ze<<<dim3(ND / 64, NBH / 128), 256, 0, st>>>(
            Ain, Wi + (long)i * NC * ND, bi + i * ND, p_ze, NC, ND, rbase);
        k_rownorm<<<NBH / 4, 128, 0, st>>>(rbase);
        k_dots<<<NBH / 128, 256, DOT_SMEM_TOTAL, st>>>(cb, rbase);
        k_argsel<<<NBH / 8, 256, 0, st>>>(cb, i, rbase);
        k_gather<<<NBH, 256, 0, st>>>(cb, out, i, writeFull, rbase);
        k_gemm_out<<<dim3(NC / 64, NBH / 128), 256, 0, st>>>(
            p_zqst, Wo + (long)i * ND * NC, bo + i * NC, out, z, ND, NC, i, rbase);
    }
}

extern "C" void kernel_launch(void* const* d_in, const int* in_sizes, int n_in,
                              void* d_out, int out_size) {
    const float* z   = (const float*)d_in[0];
    const float* cbs = (const float*)d_in[1];
    const float* Wi  = (const float*)d_in[2];
    const float* bi  = (const float*)d_in[3];
    const float* Wo  = (const float*)d_in[4];
    const float* bo  = (const float*)d_in[5];
    float* out = (float*)d_out;
    int writeFull = (out_size >= O_TOT) ? 1 : 0;

    static cudaStream_t s1 = nullptr;
    static cudaEvent_t evOff = nullptr, evJoin = nullptr;
    if (s1 == nullptr) {
        cudaStreamCreateWithFlags(&s1, cudaStreamNonBlocking);
        cudaEventCreateWithFlags(&evOff, cudaEventDisableTiming);
        cudaEventCreateWithFlags(&evJoin, cudaEventDisableTiming);
        cudaFuncSetAttribute(k_dots, cudaFuncAttributeMaxDynamicSharedMemorySize, DOT_SMEM_TOTAL);
    }

    float *p_res, *p_ze, *p_zqst;
    cudaGetSymbolAddress((void**)&p_res,  g_res);
    cudaGetSymbolAddress((void**)&p_ze,   g_ze);
    cudaGetSymbolAddress((void**)&p_zqst, g_zqst);

    // All codebook norms upfront into per-codebook slots (read-only afterwards;
    // safe for both streams regardless of phase).
    for (int i = 0; i < NCB; i++)
        k_cbn<<<NK / 4, 128>>>(cbs + (long)i * NK * ND, i);

    // Phase offset: start half-1 after half-0's first z_e GEMM so one stream's
    // GEMM (FMA pipe) overlaps the other's dots/argsel (tensor/DRAM pipes).
    k_gemm_ze<<<dim3(ND / 64, NBH / 128), 256>>>(
        z, Wi, bi, p_ze, NC, ND, 0);
    cudaEventRecord(evOff, 0);

    // Rest of half-0 pipeline on the main stream.
    {
        int rbase = 0;
        k_rownorm<<<NBH / 4, 128>>>(rbase);
        k_dots<<<NBH / 128, 256, DOT_SMEM_TOTAL>>>(cbs, rbase);
        k_argsel<<<NBH / 8, 256>>>(cbs, 0, rbase);
        k_gather<<<NBH, 256>>>(cbs, out, 0, writeFull, rbase);
        k_gemm_out<<<dim3(NC / 64, NBH / 128), 256>>>(
            p_zqst, Wo, bo, out, z, ND, NC, 0, rbase);
        for (int i = 1; i < NCB; i++) {
            const float* cb = cbs + (long)i * NK * ND;
            k_gemm_ze<<<dim3(ND / 64, NBH / 128), 256>>>(
                p_res, Wi + (long)i * NC * ND, bi + i * ND, p_ze, NC, ND, rbase);
            k_rownorm<<<NBH / 4, 128>>>(rbase);
            k_dots<<<NBH / 128, 256, DOT_SMEM_TOTAL>>>(cb, rbase);
            k_argsel<<<NBH / 8, 256>>>(cb, i, rbase);
            k_gather<<<NBH, 256>>>(cb, out, i, writeFull, rbase);
            k_gemm_out<<<dim3(NC / 64, NBH / 128), 256>>>(
                p_zqst, Wo + (long)i * ND * NC, bo + i * NC, out, z, ND, NC, i, rbase);
        }
    }

    // Half-1 pipeline on side stream, offset by one GEMM.
    cudaStreamWaitEvent(s1, evOff, 0);
    run_half(s1, NBH, z, cbs, Wi, bi, Wo, bo, out, writeFull, p_res, p_ze, p_zqst);
    cudaEventRecord(evJoin, s1);
    cudaStreamWaitEvent(0, evJoin, 0);

    k_loss<<<1, 1024>>>(out, writeFull);
}